// round 10
// baseline (speedup 1.0000x reference)
#include <cuda_runtime.h>
#include <cuda_bf16.h>
#include <math.h>

// Problem constants
#define BB 16
#define MM 256
#define TT 128
#define DD 512
#define HH 8
#define LL 4
#define VV 32000
#define HD 64
#define BT (BB*TT)     // 2048
#define BM_ROWS (BB*MM) // 4096

// ---------------- scratch (static device globals; no allocation allowed) ---
__device__ float g_x[BT*DD];        // residual stream [2048,512]
__device__ float g_h[BT*DD];        // LN output
__device__ float g_attn[BT*DD];     // merged attention output
__device__ float g_q[BT*DD];        // cross-attn query
__device__ float g_qkv[BT*3*DD];    // self-attn qkv [2048,1536]
__device__ float g_kv[BM_ROWS*2*DD];// cross kv proj [4096,1024]
__device__ float g_ffn[BT*4*DD];    // ffn hidden [2048,2048]
__device__ int   g_is64;

// ---------------- targets dtype detection (int32 vs int64) ----------------
// If targets is int64 (values < 2^31), every high 32-bit word is 0.
// If int32, the words at odd indices are random token ids (won't all be 0).
__global__ void detect_kernel(const int* t) {
    __shared__ int any;
    if (threadIdx.x == 0) any = 0;
    __syncthreads();
    int local = 0;
    for (int i = threadIdx.x; i < BT/2; i += blockDim.x)
        if (t[2*i + 1] != 0) local = 1;
    if (local) atomicOr(&any, 1);
    __syncthreads();
    if (threadIdx.x == 0) g_is64 = (any == 0) ? 1 : 0;
}

// ---------------- embedding -----------------------------------------------
__global__ void embed_kernel(const void* __restrict__ targets,
                             const float* __restrict__ tok,
                             const float* __restrict__ pos,
                             float* __restrict__ x) {
    int idx = blockIdx.x * blockDim.x + threadIdx.x;
    if (idx >= BT*DD) return;
    int d  = idx & (DD-1);
    int bt = idx >> 9;          // /512
    int t  = bt & (TT-1);
    int b  = bt >> 7;           // /128
    long long token;
    if (t == 0) token = VV;     // BOS row = 32000
    else {
        int ti = b*TT + t - 1;
        token = g_is64 ? ((const long long*)targets)[ti]
                       : (long long)((const int*)targets)[ti];
    }
    x[idx] = tok[(size_t)token*DD + d] + pos[(size_t)t*DD + d];
}

// ---------------- LayerNorm (row length 512) -------------------------------
__global__ void ln_kernel(const float* __restrict__ x,
                          const float* __restrict__ g,
                          const float* __restrict__ bta,
                          float* __restrict__ o) {
    int r = blockIdx.x;
    const float* xr = x + (size_t)r * DD;
    float* orow = o + (size_t)r * DD;
    int tid = threadIdx.x;                // 256
    int w = tid >> 5, lane = tid & 31;
    __shared__ float red[8];

    float s = xr[tid] + xr[tid + 256];
    #pragma unroll
    for (int off = 16; off > 0; off >>= 1) s += __shfl_xor_sync(~0u, s, off);
    if (lane == 0) red[w] = s;
    __syncthreads();
    float tot = 0.f;
    #pragma unroll
    for (int i = 0; i < 8; i++) tot += red[i];
    float mean = tot * (1.0f / DD);
    __syncthreads();

    float d0 = xr[tid] - mean, d1 = xr[tid + 256] - mean;
    float v = d0*d0 + d1*d1;
    #pragma unroll
    for (int off = 16; off > 0; off >>= 1) v += __shfl_xor_sync(~0u, v, off);
    if (lane == 0) red[w] = v;
    __syncthreads();
    float vt = 0.f;
    #pragma unroll
    for (int i = 0; i < 8; i++) vt += red[i];
    float inv = rsqrtf(vt * (1.0f / DD) + 1e-5f);

    orow[tid]       = d0 * inv * g[tid]       + bta[tid];
    orow[tid + 256] = d1 * inv * g[tid + 256] + bta[tid + 256];
}

// ---------------- tiled SGEMM: C = A[M,K] @ B[K,N] (+bias)(+res)(gelu) ------
// BMt=BNt=64, BKt=16, 256 threads, 4x4 per-thread micro-tile.
// All M % 64 == 0, N % 64 == 0, K % 16 == 0 for this problem.
#define BMt 64
#define BNt 64
#define BKt 16

__device__ __forceinline__ float gelu_exact(float v) {
    return 0.5f * v * (1.0f + erff(v * 0.70710678118654752f));
}

template<int EPI>  // 0: +bias, 1: +bias+residual, 2: gelu(+bias)
__global__ void sgemm_kernel(const float* __restrict__ A,
                             const float* __restrict__ B,
                             const float* __restrict__ bias,
                             const float* __restrict__ R,
                             float* __restrict__ C,
                             int M, int N, int K) {
    __shared__ float  As[BKt][BMt + 4];
    __shared__ float4 Bs[BKt][BNt/4];
    int tid = threadIdx.x;          // 256
    int tx = tid & 15, ty = tid >> 4;
    int m0 = blockIdx.y * BMt, n0 = blockIdx.x * BNt;

    const float4* A4 = (const float4*)A;
    const float4* B4 = (const float4*)B;
    int K4 = K >> 2, N4 = N >> 2;

    int am = tid >> 2, akq = tid & 3;   // A: row am (0..63), float4 col akq
    int bk = tid >> 4, bn4 = tid & 15;  // B: row bk (0..15), float4 col bn4

    float acc[4][4] = {};

    for (int k0 = 0; k0 < K; k0 += BKt) {
        float4 av = A4[(size_t)(m0 + am) * K4 + (k0 >> 2) + akq];
        As[akq*4 + 0][am] = av.x;
        As[akq*4 + 1][am] = av.y;
        As[akq*4 + 2][am] = av.z;
        As[akq*4 + 3][am] = av.w;
        Bs[bk][bn4] = B4[(size_t)(k0 + bk) * N4 + (n0 >> 2) + bn4];
        __syncthreads();
        #pragma unroll
        for (int kk = 0; kk < BKt; kk++) {
            float a0 = As[kk][ty*4+0], a1 = As[kk][ty*4+1];
            float a2 = As[kk][ty*4+2], a3 = As[kk][ty*4+3];
            float4 bv = Bs[kk][tx];
            acc[0][0] += a0*bv.x; acc[0][1] += a0*bv.y; acc[0][2] += a0*bv.z; acc[0][3] += a0*bv.w;
            acc[1][0] += a1*bv.x; acc[1][1] += a1*bv.y; acc[1][2] += a1*bv.z; acc[1][3] += a1*bv.w;
            acc[2][0] += a2*bv.x; acc[2][1] += a2*bv.y; acc[2][2] += a2*bv.z; acc[2][3] += a2*bv.w;
            acc[3][0] += a3*bv.x; acc[3][1] += a3*bv.y; acc[3][2] += a3*bv.z; acc[3][3] += a3*bv.w;
        }
        __syncthreads();
    }

    float4 bi = ((const float4*)bias)[(n0 >> 2) + tx];
    #pragma unroll
    for (int i = 0; i < 4; i++) {
        int row = m0 + ty*4 + i;
        float4 v;
        v.x = acc[i][0] + bi.x; v.y = acc[i][1] + bi.y;
        v.z = acc[i][2] + bi.z; v.w = acc[i][3] + bi.w;
        if (EPI == 1) {
            float4 rv = ((const float4*)R)[(size_t)row * N4 + (n0 >> 2) + tx];
            v.x += rv.x; v.y += rv.y; v.z += rv.z; v.w += rv.w;
        } else if (EPI == 2) {
            v.x = gelu_exact(v.x); v.y = gelu_exact(v.y);
            v.z = gelu_exact(v.z); v.w = gelu_exact(v.w);
        }
        ((float4*)C)[(size_t)row * N4 + (n0 >> 2) + tx] = v;
    }
}

// ---------------- self-attention (causal, T=128 keys) ----------------------
// grid(T, B*H), 128 threads. qkv row layout: [q(512) k(512) v(512)].
__global__ void self_attn_kernel(const float* __restrict__ qkv,
                                 float* __restrict__ out) {
    int q = blockIdx.x;
    int b = blockIdx.y >> 3, h = blockIdx.y & 7;
    int tid = threadIdx.x;              // 128
    int w = tid >> 5, lane = tid & 31;

    __shared__ float sQ[HD];
    __shared__ float sc[TT];
    __shared__ float red[4];
    __shared__ float part[2][HD];

    const float* Qp = qkv + ((size_t)(b*TT + q)) * (3*DD) + h*HD;
    if (tid < HD) sQ[tid] = Qp[tid];
    __syncthreads();

    float s;
    if (tid <= q) {
        const float* Kp = qkv + ((size_t)(b*TT + tid)) * (3*DD) + DD + h*HD;
        float a = 0.f;
        #pragma unroll
        for (int d = 0; d < HD; d++) a += sQ[d] * Kp[d];
        s = a * 0.125f;                 // 1/sqrt(64)
    } else s = -1e9f;

    float m = s;
    #pragma unroll
    for (int off = 16; off > 0; off >>= 1) m = fmaxf(m, __shfl_xor_sync(~0u, m, off));
    if (lane == 0) red[w] = m;
    __syncthreads();
    float gm = fmaxf(fmaxf(red[0], red[1]), fmaxf(red[2], red[3]));
    __syncthreads();
    float e = expf(s - gm);
    float su = e;
    #pragma unroll
    for (int off = 16; off > 0; off >>= 1) su += __shfl_xor_sync(~0u, su, off);
    if (lane == 0) red[w] = su;
    sc[tid] = e;
    __syncthreads();
    float gs = red[0] + red[1] + red[2] + red[3];

    // AV: thread (d, half); each half covers 64 keys
    int d = tid & 63, half = tid >> 6;
    float a = 0.f;
    int kbase = half * 64;
    for (int kk = 0; kk < 64; kk++) {
        const float* Vp = qkv + ((size_t)(b*TT + kbase + kk)) * (3*DD) + 2*DD + h*HD;
        a += sc[kbase + kk] * Vp[d];
    }
    part[half][d] = a;
    __syncthreads();
    if (tid < HD)
        out[((size_t)(b*TT + q)) * DD + h*HD + tid] =
            (part[0][tid] + part[1][tid]) / gs;
}

// ---------------- cross-attention (M=256 keys, no mask) --------------------
// grid(T, B*H), 256 threads. kv row layout: [k(512) v(512)].
__global__ void cross_attn_kernel(const float* __restrict__ qbuf,
                                  const float* __restrict__ kv,
                                  float* __restrict__ out) {
    int q = blockIdx.x;
    int b = blockIdx.y >> 3, h = blockIdx.y & 7;
    int tid = threadIdx.x;              // 256
    int w = tid >> 5, lane = tid & 31;

    __shared__ float sQ[HD];
    __shared__ float sc[MM];
    __shared__ float red[8];
    __shared__ float part[4][HD];

    if (tid < HD) sQ[tid] = qbuf[((size_t)(b*TT + q)) * DD + h*HD + tid];
    __syncthreads();

    const float* Kp = kv + ((size_t)(b*MM + tid)) * (2*DD) + h*HD;
    float a = 0.f;
    #pragma unroll
    for (int d = 0; d < HD; d++) a += sQ[d] * Kp[d];
    float s = a * 0.125f;

    float m = s;
    #pragma unroll
    for (int off = 16; off > 0; off >>= 1) m = fmaxf(m, __shfl_xor_sync(~0u, m, off));
    if (lane == 0) red[w] = m;
    __syncthreads();
    float gm = red[0];
    #pragma unroll
    for (int i = 1; i < 8; i++) gm = fmaxf(gm, red[i]);
    __syncthreads();
    float e = expf(s - gm);
    float su = e;
    #pragma unroll
    for (int off = 16; off > 0; off >>= 1) su += __shfl_xor_sync(~0u, su, off);
    if (lane == 0) red[w] = su;
    sc[tid] = e;
    __syncthreads();
    float gs = 0.f;
    #pragma unroll
    for (int i = 0; i < 8; i++) gs += red[i];

    int d = tid & 63, qt = tid >> 6;
    float av = 0.f;
    int kbase = qt * 64;
    for (int kk = 0; kk < 64; kk++) {
        const float* Vp = kv + ((size_t)(b*MM + kbase + kk)) * (2*DD) + DD + h*HD;
        av += sc[kbase + kk] * Vp[d];
    }
    part[qt][d] = av;
    __syncthreads();
    if (tid < HD)
        out[((size_t)(b*TT + q)) * DD + h*HD + tid] =
            (part[0][tid] + part[1][tid] + part[2][tid] + part[3][tid]) / gs;
}

// ---------------- host orchestration ---------------------------------------
static inline void run_gemm(int epi, const float* A, const float* B,
                            const float* bias, const float* R, float* C,
                            int M, int N, int K) {
    dim3 grid(N / BNt, M / BMt);
    if (epi == 0)      sgemm_kernel<0><<<grid, 256>>>(A, B, bias, R, C, M, N, K);
    else if (epi == 1) sgemm_kernel<1><<<grid, 256>>>(A, B, bias, R, C, M, N, K);
    else               sgemm_kernel<2><<<grid, 256>>>(A, B, bias, R, C, M, N, K);
}

extern "C" void kernel_launch(void* const* d_in, const int* in_sizes, int n_in,
                              void* d_out, int out_size) {
    const float* memory  = (const float*)d_in[0];
    const void*  targets = d_in[1];
    const float* tok_emb = (const float*)d_in[2];
    const float* pos_emb = (const float*)d_in[3];
    const float* sa_qkv_w = (const float*)d_in[4];
    const float* sa_qkv_b = (const float*)d_in[5];
    const float* sa_out_w = (const float*)d_in[6];
    const float* sa_out_b = (const float*)d_in[7];
    const float* ca_q_w   = (const float*)d_in[8];
    const float* ca_q_b   = (const float*)d_in[9];
    const float* ca_kv_w  = (const float*)d_in[10];
    const float* ca_kv_b  = (const float*)d_in[11];
    const float* ca_out_w = (const float*)d_in[12];
    const float* ca_out_b = (const float*)d_in[13];
    const float* ffn1_w   = (const float*)d_in[14];
    const float* ffn1_b   = (const float*)d_in[15];
    const float* ffn2_w   = (const float*)d_in[16];
    const float* ffn2_b   = (const float*)d_in[17];
    const float* ln1_g = (const float*)d_in[18];
    const float* ln1_b = (const float*)d_in[19];
    const float* ln2_g = (const float*)d_in[20];
    const float* ln2_b = (const float*)d_in[21];
    const float* ln3_g = (const float*)d_in[22];
    const float* ln3_b = (const float*)d_in[23];
    const float* normf_g = (const float*)d_in[24];
    const float* normf_b = (const float*)d_in[25];
    const float* out_w = (const float*)d_in[26];
    const float* out_b = (const float*)d_in[27];
    float* out = (float*)d_out;

    float *x, *h, *attn, *qb, *qkv, *kv, *ffn;
    cudaGetSymbolAddress((void**)&x,    g_x);
    cudaGetSymbolAddress((void**)&h,    g_h);
    cudaGetSymbolAddress((void**)&attn, g_attn);
    cudaGetSymbolAddress((void**)&qb,   g_q);
    cudaGetSymbolAddress((void**)&qkv,  g_qkv);
    cudaGetSymbolAddress((void**)&kv,   g_kv);
    cudaGetSymbolAddress((void**)&ffn,  g_ffn);

    detect_kernel<<<1, 256>>>((const int*)targets);
    embed_kernel<<<(BT*DD + 255) / 256, 256>>>(targets, tok_emb, pos_emb, x);

    dim3 agrid(TT, BB*HH);

    for (int l = 0; l < LL; l++) {
        // ---- self-attention ----
        ln_kernel<<<BT, 256>>>(x, ln1_g + l*DD, ln1_b + l*DD, h);
        run_gemm(0, h, sa_qkv_w + (size_t)l*DD*3*DD, sa_qkv_b + (size_t)l*3*DD,
                 nullptr, qkv, BT, 3*DD, DD);
        self_attn_kernel<<<agrid, 128>>>(qkv, attn);
        run_gemm(1, attn, sa_out_w + (size_t)l*DD*DD, sa_out_b + (size_t)l*DD,
                 x, x, BT, DD, DD);
        // ---- cross-attention ----
        ln_kernel<<<BT, 256>>>(x, ln2_g + l*DD, ln2_b + l*DD, h);
        run_gemm(0, h, ca_q_w + (size_t)l*DD*DD, ca_q_b + (size_t)l*DD,
                 nullptr, qb, BT, DD, DD);
        run_gemm(0, memory, ca_kv_w + (size_t)l*DD*2*DD, ca_kv_b + (size_t)l*2*DD,
                 nullptr, kv, BM_ROWS, 2*DD, DD);
        cross_attn_kernel<<<agrid, 256>>>(qb, kv, attn);
        run_gemm(1, attn, ca_out_w + (size_t)l*DD*DD, ca_out_b + (size_t)l*DD,
                 x, x, BT, DD, DD);
        // ---- FFN ----
        ln_kernel<<<BT, 256>>>(x, ln3_g + l*DD, ln3_b + l*DD, h);
        run_gemm(2, h, ffn1_w + (size_t)l*DD*4*DD, ffn1_b + (size_t)l*4*DD,
                 nullptr, ffn, BT, 4*DD, DD);
        run_gemm(1, ffn, ffn2_w + (size_t)l*4*DD*DD, ffn2_b + (size_t)l*DD,
                 x, x, BT, DD, 4*DD);
    }

    // ---- final LN + vocab head ----
    ln_kernel<<<BT, 256>>>(x, normf_g, normf_b, h);
    run_gemm(0, h, out_w, out_b, nullptr, out, BT, VV, DD);
}

// round 12
// speedup vs baseline: 1.0006x; 1.0006x over previous
#include <cuda_runtime.h>
#include <cuda_bf16.h>
#include <math.h>

// Problem constants
#define BB 16
#define MM 256
#define TT 128
#define DD 512
#define HH 8
#define LL 4
#define VV 32000
#define HD 64
#define BT (BB*TT)     // 2048
#define BM_ROWS (BB*MM) // 4096

// ---------------- scratch (static device globals; no allocation allowed) ---
__device__ float g_x[BT*DD];        // residual stream [2048,512]
__device__ float g_h[BT*DD];        // LN output
__device__ float g_attn[BT*DD];     // merged attention output
__device__ float g_q[BT*DD];        // cross-attn query
__device__ float g_qkv[BT*3*DD];    // self-attn qkv [2048,1536]
__device__ float g_kv[BM_ROWS*2*DD];// cross kv proj [4096,1024]
__device__ float g_ffn[BT*4*DD];    // ffn hidden [2048,2048]
__device__ int   g_is64;

// ---------------- targets dtype detection (int32 vs int64) ----------------
// If targets is int64 (values < 2^31), every high 32-bit word is 0.
// If int32, the words at odd indices are random token ids (won't all be 0).
__global__ void detect_kernel(const int* t) {
    __shared__ int any;
    if (threadIdx.x == 0) any = 0;
    __syncthreads();
    int local = 0;
    for (int i = threadIdx.x; i < BT/2; i += blockDim.x)
        if (t[2*i + 1] != 0) local = 1;
    if (local) atomicOr(&any, 1);
    __syncthreads();
    if (threadIdx.x == 0) g_is64 = (any == 0) ? 1 : 0;
}

// ---------------- embedding -----------------------------------------------
__global__ void embed_kernel(const void* __restrict__ targets,
                             const float* __restrict__ tok,
                             const float* __restrict__ pos,
                             float* __restrict__ x) {
    int idx = blockIdx.x * blockDim.x + threadIdx.x;
    if (idx >= BT*DD) return;
    int d  = idx & (DD-1);
    int bt = idx >> 9;          // /512
    int t  = bt & (TT-1);
    int b  = bt >> 7;           // /128
    long long token;
    if (t == 0) token = VV;     // BOS row = 32000
    else {
        int ti = b*TT + t - 1;
        token = g_is64 ? ((const long long*)targets)[ti]
                       : (long long)((const int*)targets)[ti];
    }
    x[idx] = tok[(size_t)token*DD + d] + pos[(size_t)t*DD + d];
}

// ---------------- LayerNorm (row length 512) -------------------------------
__global__ void ln_kernel(const float* __restrict__ x,
                          const float* __restrict__ g,
                          const float* __restrict__ bta,
                          float* __restrict__ o) {
    int r = blockIdx.x;
    const float* xr = x + (size_t)r * DD;
    float* orow = o + (size_t)r * DD;
    int tid = threadIdx.x;                // 256
    int w = tid >> 5, lane = tid & 31;
    __shared__ float red[8];

    float s = xr[tid] + xr[tid + 256];
    #pragma unroll
    for (int off = 16; off > 0; off >>= 1) s += __shfl_xor_sync(~0u, s, off);
    if (lane == 0) red[w] = s;
    __syncthreads();
    float tot = 0.f;
    #pragma unroll
    for (int i = 0; i < 8; i++) tot += red[i];
    float mean = tot * (1.0f / DD);
    __syncthreads();

    float d0 = xr[tid] - mean, d1 = xr[tid + 256] - mean;
    float v = d0*d0 + d1*d1;
    #pragma unroll
    for (int off = 16; off > 0; off >>= 1) v += __shfl_xor_sync(~0u, v, off);
    if (lane == 0) red[w] = v;
    __syncthreads();
    float vt = 0.f;
    #pragma unroll
    for (int i = 0; i < 8; i++) vt += red[i];
    float inv = rsqrtf(vt * (1.0f / DD) + 1e-5f);

    orow[tid]       = d0 * inv * g[tid]       + bta[tid];
    orow[tid + 256] = d1 * inv * g[tid + 256] + bta[tid + 256];
}

// ---------------- tiled SGEMM: C = A[M,K] @ B[K,N] (+bias)(+res)(gelu) ------
// BMt=BNt=64, BKt=16, 256 threads, 4x4 per-thread micro-tile.
// All M % 64 == 0, N % 64 == 0, K % 16 == 0 for this problem.
#define BMt 64
#define BNt 64
#define BKt 16

__device__ __forceinline__ float gelu_exact(float v) {
    return 0.5f * v * (1.0f + erff(v * 0.70710678118654752f));
}

template<int EPI>  // 0: +bias, 1: +bias+residual, 2: gelu(+bias)
__global__ void sgemm_kernel(const float* __restrict__ A,
                             const float* __restrict__ B,
                             const float* __restrict__ bias,
                             const float* __restrict__ R,
                             float* __restrict__ C,
                             int M, int N, int K) {
    __shared__ float  As[BKt][BMt + 4];
    __shared__ float4 Bs[BKt][BNt/4];
    int tid = threadIdx.x;          // 256
    int tx = tid & 15, ty = tid >> 4;
    int m0 = blockIdx.y * BMt, n0 = blockIdx.x * BNt;

    const float4* A4 = (const float4*)A;
    const float4* B4 = (const float4*)B;
    int K4 = K >> 2, N4 = N >> 2;

    int am = tid >> 2, akq = tid & 3;   // A: row am (0..63), float4 col akq
    int bk = tid >> 4, bn4 = tid & 15;  // B: row bk (0..15), float4 col bn4

    float acc[4][4] = {};

    for (int k0 = 0; k0 < K; k0 += BKt) {
        float4 av = A4[(size_t)(m0 + am) * K4 + (k0 >> 2) + akq];
        As[akq*4 + 0][am] = av.x;
        As[akq*4 + 1][am] = av.y;
        As[akq*4 + 2][am] = av.z;
        As[akq*4 + 3][am] = av.w;
        Bs[bk][bn4] = B4[(size_t)(k0 + bk) * N4 + (n0 >> 2) + bn4];
        __syncthreads();
        #pragma unroll
        for (int kk = 0; kk < BKt; kk++) {
            float a0 = As[kk][ty*4+0], a1 = As[kk][ty*4+1];
            float a2 = As[kk][ty*4+2], a3 = As[kk][ty*4+3];
            float4 bv = Bs[kk][tx];
            acc[0][0] += a0*bv.x; acc[0][1] += a0*bv.y; acc[0][2] += a0*bv.z; acc[0][3] += a0*bv.w;
            acc[1][0] += a1*bv.x; acc[1][1] += a1*bv.y; acc[1][2] += a1*bv.z; acc[1][3] += a1*bv.w;
            acc[2][0] += a2*bv.x; acc[2][1] += a2*bv.y; acc[2][2] += a2*bv.z; acc[2][3] += a2*bv.w;
            acc[3][0] += a3*bv.x; acc[3][1] += a3*bv.y; acc[3][2] += a3*bv.z; acc[3][3] += a3*bv.w;
        }
        __syncthreads();
    }

    float4 bi = ((const float4*)bias)[(n0 >> 2) + tx];
    #pragma unroll
    for (int i = 0; i < 4; i++) {
        int row = m0 + ty*4 + i;
        float4 v;
        v.x = acc[i][0] + bi.x; v.y = acc[i][1] + bi.y;
        v.z = acc[i][2] + bi.z; v.w = acc[i][3] + bi.w;
        if (EPI == 1) {
            float4 rv = ((const float4*)R)[(size_t)row * N4 + (n0 >> 2) + tx];
            v.x += rv.x; v.y += rv.y; v.z += rv.z; v.w += rv.w;
        } else if (EPI == 2) {
            v.x = gelu_exact(v.x); v.y = gelu_exact(v.y);
            v.z = gelu_exact(v.z); v.w = gelu_exact(v.w);
        }
        ((float4*)C)[(size_t)row * N4 + (n0 >> 2) + tx] = v;
    }
}

// ---------------- self-attention (causal, T=128 keys) ----------------------
// grid(T, B*H), 128 threads. qkv row layout: [q(512) k(512) v(512)].
__global__ void self_attn_kernel(const float* __restrict__ qkv,
                                 float* __restrict__ out) {
    int q = blockIdx.x;
    int b = blockIdx.y >> 3, h = blockIdx.y & 7;
    int tid = threadIdx.x;              // 128
    int w = tid >> 5, lane = tid & 31;

    __shared__ float sQ[HD];
    __shared__ float sc[TT];
    __shared__ float red[4];
    __shared__ float part[2][HD];

    const float* Qp = qkv + ((size_t)(b*TT + q)) * (3*DD) + h*HD;
    if (tid < HD) sQ[tid] = Qp[tid];
    __syncthreads();

    float s;
    if (tid <= q) {
        const float* Kp = qkv + ((size_t)(b*TT + tid)) * (3*DD) + DD + h*HD;
        float a = 0.f;
        #pragma unroll
        for (int d = 0; d < HD; d++) a += sQ[d] * Kp[d];
        s = a * 0.125f;                 // 1/sqrt(64)
    } else s = -1e9f;

    float m = s;
    #pragma unroll
    for (int off = 16; off > 0; off >>= 1) m = fmaxf(m, __shfl_xor_sync(~0u, m, off));
    if (lane == 0) red[w] = m;
    __syncthreads();
    float gm = fmaxf(fmaxf(red[0], red[1]), fmaxf(red[2], red[3]));
    __syncthreads();
    float e = expf(s - gm);
    float su = e;
    #pragma unroll
    for (int off = 16; off > 0; off >>= 1) su += __shfl_xor_sync(~0u, su, off);
    if (lane == 0) red[w] = su;
    sc[tid] = e;
    __syncthreads();
    float gs = red[0] + red[1] + red[2] + red[3];

    // AV: thread (d, half); each half covers 64 keys
    int d = tid & 63, half = tid >> 6;
    float a = 0.f;
    int kbase = half * 64;
    for (int kk = 0; kk < 64; kk++) {
        const float* Vp = qkv + ((size_t)(b*TT + kbase + kk)) * (3*DD) + 2*DD + h*HD;
        a += sc[kbase + kk] * Vp[d];
    }
    part[half][d] = a;
    __syncthreads();
    if (tid < HD)
        out[((size_t)(b*TT + q)) * DD + h*HD + tid] =
            (part[0][tid] + part[1][tid]) / gs;
}

// ---------------- cross-attention (M=256 keys, no mask) --------------------
// grid(T, B*H), 256 threads. kv row layout: [k(512) v(512)].
__global__ void cross_attn_kernel(const float* __restrict__ qbuf,
                                  const float* __restrict__ kv,
                                  float* __restrict__ out) {
    int q = blockIdx.x;
    int b = blockIdx.y >> 3, h = blockIdx.y & 7;
    int tid = threadIdx.x;              // 256
    int w = tid >> 5, lane = tid & 31;

    __shared__ float sQ[HD];
    __shared__ float sc[MM];
    __shared__ float red[8];
    __shared__ float part[4][HD];

    if (tid < HD) sQ[tid] = qbuf[((size_t)(b*TT + q)) * DD + h*HD + tid];
    __syncthreads();

    const float* Kp = kv + ((size_t)(b*MM + tid)) * (2*DD) + h*HD;
    float a = 0.f;
    #pragma unroll
    for (int d = 0; d < HD; d++) a += sQ[d] * Kp[d];
    float s = a * 0.125f;

    float m = s;
    #pragma unroll
    for (int off = 16; off > 0; off >>= 1) m = fmaxf(m, __shfl_xor_sync(~0u, m, off));
    if (lane == 0) red[w] = m;
    __syncthreads();
    float gm = red[0];
    #pragma unroll
    for (int i = 1; i < 8; i++) gm = fmaxf(gm, red[i]);
    __syncthreads();
    float e = expf(s - gm);
    float su = e;
    #pragma unroll
    for (int off = 16; off > 0; off >>= 1) su += __shfl_xor_sync(~0u, su, off);
    if (lane == 0) red[w] = su;
    sc[tid] = e;
    __syncthreads();
    float gs = 0.f;
    #pragma unroll
    for (int i = 0; i < 8; i++) gs += red[i];

    int d = tid & 63, qt = tid >> 6;
    float av = 0.f;
    int kbase = qt * 64;
    for (int kk = 0; kk < 64; kk++) {
        const float* Vp = kv + ((size_t)(b*MM + kbase + kk)) * (2*DD) + DD + h*HD;
        av += sc[kbase + kk] * Vp[d];
    }
    part[qt][d] = av;
    __syncthreads();
    if (tid < HD)
        out[((size_t)(b*TT + q)) * DD + h*HD + tid] =
            (part[0][tid] + part[1][tid] + part[2][tid] + part[3][tid]) / gs;
}

// ---------------- host orchestration ---------------------------------------
static inline void run_gemm(int epi, const float* A, const float* B,
                            const float* bias, const float* R, float* C,
                            int M, int N, int K) {
    dim3 grid(N / BNt, M / BMt);
    if (epi == 0)      sgemm_kernel<0><<<grid, 256>>>(A, B, bias, R, C, M, N, K);
    else if (epi == 1) sgemm_kernel<1><<<grid, 256>>>(A, B, bias, R, C, M, N, K);
    else               sgemm_kernel<2><<<grid, 256>>>(A, B, bias, R, C, M, N, K);
}

extern "C" void kernel_launch(void* const* d_in, const int* in_sizes, int n_in,
                              void* d_out, int out_size) {
    const float* memory  = (const float*)d_in[0];
    const void*  targets = d_in[1];
    const float* tok_emb = (const float*)d_in[2];
    const float* pos_emb = (const float*)d_in[3];
    const float* sa_qkv_w = (const float*)d_in[4];
    const float* sa_qkv_b = (const float*)d_in[5];
    const float* sa_out_w = (const float*)d_in[6];
    const float* sa_out_b = (const float*)d_in[7];
    const float* ca_q_w   = (const float*)d_in[8];
    const float* ca_q_b   = (const float*)d_in[9];
    const float* ca_kv_w  = (const float*)d_in[10];
    const float* ca_kv_b  = (const float*)d_in[11];
    const float* ca_out_w = (const float*)d_in[12];
    const float* ca_out_b = (const float*)d_in[13];
    const float* ffn1_w   = (const float*)d_in[14];
    const float* ffn1_b   = (const float*)d_in[15];
    const float* ffn2_w   = (const float*)d_in[16];
    const float* ffn2_b   = (const float*)d_in[17];
    const float* ln1_g = (const float*)d_in[18];
    const float* ln1_b = (const float*)d_in[19];
    const float* ln2_g = (const float*)d_in[20];
    const float* ln2_b = (const float*)d_in[21];
    const float* ln3_g = (const float*)d_in[22];
    const float* ln3_b = (const float*)d_in[23];
    const float* normf_g = (const float*)d_in[24];
    const float* normf_b = (const float*)d_in[25];
    const float* out_w = (const float*)d_in[26];
    const float* out_b = (const float*)d_in[27];
    float* out = (float*)d_out;

    float *x, *h, *attn, *qb, *qkv, *kv, *ffn;
    cudaGetSymbolAddress((void**)&x,    g_x);
    cudaGetSymbolAddress((void**)&h,    g_h);
    cudaGetSymbolAddress((void**)&attn, g_attn);
    cudaGetSymbolAddress((void**)&qb,   g_q);
    cudaGetSymbolAddress((void**)&qkv,  g_qkv);
    cudaGetSymbolAddress((void**)&kv,   g_kv);
    cudaGetSymbolAddress((void**)&ffn,  g_ffn);

    detect_kernel<<<1, 256>>>((const int*)targets);
    embed_kernel<<<(BT*DD + 255) / 256, 256>>>(targets, tok_emb, pos_emb, x);

    dim3 agrid(TT, BB*HH);

    for (int l = 0; l < LL; l++) {
        // ---- self-attention ----
        ln_kernel<<<BT, 256>>>(x, ln1_g + l*DD, ln1_b + l*DD, h);
        run_gemm(0, h, sa_qkv_w + (size_t)l*DD*3*DD, sa_qkv_b + (size_t)l*3*DD,
                 nullptr, qkv, BT, 3*DD, DD);
        self_attn_kernel<<<agrid, 128>>>(qkv, attn);
        run_gemm(1, attn, sa_out_w + (size_t)l*DD*DD, sa_out_b + (size_t)l*DD,
                 x, x, BT, DD, DD);
        // ---- cross-attention ----
        ln_kernel<<<BT, 256>>>(x, ln2_g + l*DD, ln2_b + l*DD, h);
        run_gemm(0, h, ca_q_w + (size_t)l*DD*DD, ca_q_b + (size_t)l*DD,
                 nullptr, qb, BT, DD, DD);
        run_gemm(0, memory, ca_kv_w + (size_t)l*DD*2*DD, ca_kv_b + (size_t)l*2*DD,
                 nullptr, kv, BM_ROWS, 2*DD, DD);
        cross_attn_kernel<<<agrid, 256>>>(qb, kv, attn);
        run_gemm(1, attn, ca_out_w + (size_t)l*DD*DD, ca_out_b + (size_t)l*DD,
                 x, x, BT, DD, DD);
        // ---- FFN ----
        ln_kernel<<<BT, 256>>>(x, ln3_g + l*DD, ln3_b + l*DD, h);
        run_gemm(2, h, ffn1_w + (size_t)l*DD*4*DD, ffn1_b + (size_t)l*4*DD,
                 nullptr, ffn, BT, 4*DD, DD);
        run_gemm(1, ffn, ffn2_w + (size_t)l*4*DD*DD, ffn2_b + (size_t)l*DD,
                 x, x, BT, DD, 4*DD);
    }

    // ---- final LN + vocab head ----
    ln_kernel<<<BT, 256>>>(x, normf_g, normf_b, h);
    run_gemm(0, h, out_w, out_b, nullptr, out, BT, VV, DD);
}

// round 13
// speedup vs baseline: 1.2483x; 1.2476x over previous
#include <cuda_runtime.h>
#include <cuda_bf16.h>
#include <math.h>
#include <stdint.h>

// Problem constants
#define BB 16
#define MM 256
#define TT 128
#define DD 512
#define HH 8
#define LL 4
#define VV 32000
#define HD 64
#define BT (BB*TT)      // 2048
#define BM_ROWS (BB*MM) // 4096

// ---------------- scratch (static device globals) --------------------------
__device__ float g_x[BT*DD];
__device__ float g_h[BT*DD];
__device__ float g_attn[BT*DD];
__device__ float g_q[BT*DD];
__device__ float g_qkv[BT*3*DD];
__device__ float g_kv[BM_ROWS*2*DD];
__device__ float g_ffn[BT*4*DD];
__device__ int   g_is64;

// split-bf16 operand buffers
__device__ __nv_bfloat16 g_Ab[BT * 3 * 4 * DD];          // max A: [2048, 3*2048]
__device__ __nv_bfloat16 g_memb[BM_ROWS * 3 * DD];       // converted memory [4096,1536]
__device__ __nv_bfloat16 g_Bb[3 * DD * VV];              // max B: [1536, 32000]

// ---------------- dtype detection ------------------------------------------
__global__ void detect_kernel(const int* t) {
    __shared__ int any;
    if (threadIdx.x == 0) any = 0;
    __syncthreads();
    int local = 0;
    for (int i = threadIdx.x; i < BT/2; i += blockDim.x)
        if (t[2*i + 1] != 0) local = 1;
    if (local) atomicOr(&any, 1);
    __syncthreads();
    if (threadIdx.x == 0) g_is64 = (any == 0) ? 1 : 0;
}

// ---------------- embedding -------------------------------------------------
__global__ void embed_kernel(const void* __restrict__ targets,
                             const float* __restrict__ tok,
                             const float* __restrict__ pos,
                             float* __restrict__ x) {
    int idx = blockIdx.x * blockDim.x + threadIdx.x;
    if (idx >= BT*DD) return;
    int d  = idx & (DD-1);
    int bt = idx >> 9;
    int t  = bt & (TT-1);
    int b  = bt >> 7;
    long long token;
    if (t == 0) token = VV;
    else {
        int ti = b*TT + t - 1;
        token = g_is64 ? ((const long long*)targets)[ti]
                       : (long long)((const int*)targets)[ti];
    }
    x[idx] = tok[(size_t)token*DD + d] + pos[(size_t)t*DD + d];
}

// ---------------- LayerNorm -------------------------------------------------
__global__ void ln_kernel(const float* __restrict__ x,
                          const float* __restrict__ g,
                          const float* __restrict__ bta,
                          float* __restrict__ o) {
    int r = blockIdx.x;
    const float* xr = x + (size_t)r * DD;
    float* orow = o + (size_t)r * DD;
    int tid = threadIdx.x;                // 256
    int w = tid >> 5, lane = tid & 31;
    __shared__ float red[8];

    float s = xr[tid] + xr[tid + 256];
    #pragma unroll
    for (int off = 16; off > 0; off >>= 1) s += __shfl_xor_sync(~0u, s, off);
    if (lane == 0) red[w] = s;
    __syncthreads();
    float tot = 0.f;
    #pragma unroll
    for (int i = 0; i < 8; i++) tot += red[i];
    float mean = tot * (1.0f / DD);
    __syncthreads();

    float d0 = xr[tid] - mean, d1 = xr[tid + 256] - mean;
    float v = d0*d0 + d1*d1;
    #pragma unroll
    for (int off = 16; off > 0; off >>= 1) v += __shfl_xor_sync(~0u, v, off);
    if (lane == 0) red[w] = v;
    __syncthreads();
    float vt = 0.f;
    #pragma unroll
    for (int i = 0; i < 8; i++) vt += red[i];
    float inv = rsqrtf(vt * (1.0f / DD) + 1e-5f);

    orow[tid]       = d0 * inv * g[tid]       + bta[tid];
    orow[tid + 256] = d1 * inv * g[tid + 256] + bta[tid + 256];
}

// ---------------- split-bf16 conversion --------------------------------------
__device__ __forceinline__ uint32_t pack_hi(float a, float b) {
    __nv_bfloat162 t = __floats2bfloat162_rn(a, b);
    return *reinterpret_cast<uint32_t*>(&t);
}

// A fp32 [M,K] -> A'' bf16 [M, 3K] = [hi | lo | hi]
__global__ void convA_kernel(const float* __restrict__ src,
                             __nv_bfloat16* __restrict__ dst,
                             int K, int total4) {
    int idx = blockIdx.x * blockDim.x + threadIdx.x;
    if (idx >= total4) return;
    int K4 = K >> 2;
    int m = idx / K4, kq = idx - m * K4;
    float4 v = ((const float4*)src)[idx];
    __nv_bfloat16 h0 = __float2bfloat16(v.x), h1 = __float2bfloat16(v.y);
    __nv_bfloat16 h2 = __float2bfloat16(v.z), h3 = __float2bfloat16(v.w);
    float l0 = v.x - __bfloat162float(h0), l1 = v.y - __bfloat162float(h1);
    float l2 = v.z - __bfloat162float(h2), l3 = v.w - __bfloat162float(h3);
    __nv_bfloat162 hA = __nv_bfloat162(h0, h1), hB = __nv_bfloat162(h2, h3);
    uint32_t hiA = *reinterpret_cast<uint32_t*>(&hA);
    uint32_t hiB = *reinterpret_cast<uint32_t*>(&hB);
    uint32_t loA = pack_hi(l0, l1), loB = pack_hi(l2, l3);
    size_t base = (size_t)m * (3*K) + 4*kq;
    uint2* d = (uint2*)dst;
    d[base >> 2]                      = make_uint2(hiA, hiB);
    d[(base + (size_t)K) >> 2]        = make_uint2(loA, loB);
    d[(base + (size_t)2*K) >> 2]      = make_uint2(hiA, hiB);
}

// B fp32 [K,N] -> B'' bf16 [3K, N] = [hi ; hi ; lo]
__global__ void convB_kernel(const float* __restrict__ src,
                             __nv_bfloat16* __restrict__ dst,
                             int KN4, int total4) {
    int idx = blockIdx.x * blockDim.x + threadIdx.x;
    if (idx >= total4) return;
    float4 v = ((const float4*)src)[idx];
    __nv_bfloat16 h0 = __float2bfloat16(v.x), h1 = __float2bfloat16(v.y);
    __nv_bfloat16 h2 = __float2bfloat16(v.z), h3 = __float2bfloat16(v.w);
    float l0 = v.x - __bfloat162float(h0), l1 = v.y - __bfloat162float(h1);
    float l2 = v.z - __bfloat162float(h2), l3 = v.w - __bfloat162float(h3);
    __nv_bfloat162 hA = __nv_bfloat162(h0, h1), hB = __nv_bfloat162(h2, h3);
    uint32_t hiA = *reinterpret_cast<uint32_t*>(&hA);
    uint32_t hiB = *reinterpret_cast<uint32_t*>(&hB);
    uint32_t loA = pack_hi(l0, l1), loB = pack_hi(l2, l3);
    uint2* d = (uint2*)dst;
    d[idx]             = make_uint2(hiA, hiB);
    d[idx + KN4]       = make_uint2(hiA, hiB);
    d[idx + 2*KN4]     = make_uint2(loA, loB);
}

// ---------------- tensor-core GEMM ------------------------------------------
// C[M,N] = A''[M,K2] @ B''[K2,N]  (bf16 in, fp32 accum/out)
// 128x128 tile, BK=32, 8 warps (2m x 4n), each warp 64x32 via m16n8k16.
#define GBM 128
#define GBN 128
#define GBK 32
#define AS_STR 56    // elements per smem A row (112B = 7*16, coprime w/ 8)
#define BS_STR 136   // elements per smem B row (272B = 17*16, coprime w/ 8)

__device__ __forceinline__ float gelu_exact(float v) {
    return 0.5f * v * (1.0f + erff(v * 0.70710678118654752f));
}

__device__ __forceinline__ void mma16816(float* d, const uint32_t* a, const uint32_t* b) {
    asm volatile(
        "mma.sync.aligned.m16n8k16.row.col.f32.bf16.bf16.f32 "
        "{%0,%1,%2,%3}, {%4,%5,%6,%7}, {%8,%9}, {%0,%1,%2,%3};"
        : "+f"(d[0]), "+f"(d[1]), "+f"(d[2]), "+f"(d[3])
        : "r"(a[0]), "r"(a[1]), "r"(a[2]), "r"(a[3]), "r"(b[0]), "r"(b[1]));
}
__device__ __forceinline__ void ldsm_x4(uint32_t* r, uint32_t addr) {
    asm volatile("ldmatrix.sync.aligned.m8n8.x4.shared.b16 {%0,%1,%2,%3}, [%4];"
        : "=r"(r[0]), "=r"(r[1]), "=r"(r[2]), "=r"(r[3]) : "r"(addr));
}
__device__ __forceinline__ void ldsm_x4_t(uint32_t* r, uint32_t addr) {
    asm volatile("ldmatrix.sync.aligned.m8n8.x4.trans.shared.b16 {%0,%1,%2,%3}, [%4];"
        : "=r"(r[0]), "=r"(r[1]), "=r"(r[2]), "=r"(r[3]) : "r"(addr));
}

template<int EPI>  // 0: +bias ; 1: +bias+residual ; 2: gelu(+bias)
__global__ __launch_bounds__(256)
void mma_gemm(const __nv_bfloat16* __restrict__ A,
              const __nv_bfloat16* __restrict__ B,
              const float* __restrict__ bias,
              const float* __restrict__ R,
              float* __restrict__ C,
              int M, int N, int K2) {
    __shared__ __align__(16) __nv_bfloat16 As[2][GBM * AS_STR];
    __shared__ __align__(16) __nv_bfloat16 Bs[2][GBK * BS_STR];

    int tid = threadIdx.x;
    int lane = tid & 31, wid = tid >> 5;
    int wm = wid >> 2, wn = wid & 3;
    int m0 = blockIdx.y * GBM, n0 = blockIdx.x * GBN;

    // ---- global load mapping (16B chunks) ----
    int arow = tid >> 2, akc = tid & 3;      // A: rows arow, arow+64 ; k-chunk akc
    int brow = tid >> 4, bnc = tid & 15;     // B: rows brow, brow+16 ; n-chunk bnc
    size_t aG0 = (size_t)(m0 + arow) * K2 + akc*8;
    size_t aG1 = (size_t)(m0 + arow + 64) * K2 + akc*8;
    size_t bG0 = (size_t)brow * N + n0 + bnc*8;
    size_t bG1 = bG0 + (size_t)16 * N;
    int sa0 = arow*AS_STR + akc*8, sa1 = (arow+64)*AS_STR + akc*8;
    int sb0 = brow*BS_STR + bnc*8, sb1 = sb0 + 16*BS_STR;

    // ---- ldmatrix address offsets (bytes within one buffer) ----
    uint32_t as_u32 = (uint32_t)__cvta_generic_to_shared(&As[0][0]);
    uint32_t bs_u32 = (uint32_t)__cvta_generic_to_shared(&Bs[0][0]);
    const uint32_t ABYTES = GBM * AS_STR * 2;
    const uint32_t BBYTES = GBK * BS_STR * 2;
    int arl = wm*64 + (lane & 15);
    uint32_t aoffs[4];
    #pragma unroll
    for (int i = 0; i < 4; i++)
        aoffs[i] = (uint32_t)((arl + i*16) * (AS_STR*2) + (lane >> 4) * 16);
    uint32_t boffs[2];
    #pragma unroll
    for (int g = 0; g < 2; g++)
        boffs[g] = (uint32_t)((lane & 15) * (BS_STR*2)
                 + (wn*32 + g*16 + (lane >> 4)*8) * 2);

    float acc[4][4][4] = {};
    int ntiles = K2 / GBK;

    // preload tile 0
    {
        uint4 ra0 = *(const uint4*)(A + aG0);
        uint4 ra1 = *(const uint4*)(A + aG1);
        uint4 rb0 = *(const uint4*)(B + bG0);
        uint4 rb1 = *(const uint4*)(B + bG1);
        *(uint4*)&As[0][sa0] = ra0;  *(uint4*)&As[0][sa1] = ra1;
        *(uint4*)&Bs[0][sb0] = rb0;  *(uint4*)&Bs[0][sb1] = rb1;
    }
    __syncthreads();

    int buf = 0;
    for (int t = 0; t < ntiles; t++) {
        uint4 ra0, ra1, rb0, rb1;
        bool has = (t + 1 < ntiles);
        if (has) {
            size_t ka = (size_t)(t+1) * GBK;
            ra0 = *(const uint4*)(A + aG0 + ka);
            ra1 = *(const uint4*)(A + aG1 + ka);
            size_t kb = (size_t)(t+1) * GBK * N;
            rb0 = *(const uint4*)(B + bG0 + kb);
            rb1 = *(const uint4*)(B + bG1 + kb);
        }
        uint32_t abuf = as_u32 + buf*ABYTES;
        uint32_t bbuf = bs_u32 + buf*BBYTES;
        #pragma unroll
        for (int kk = 0; kk < 2; kk++) {
            uint32_t a[4][4], b[2][4];
            #pragma unroll
            for (int i = 0; i < 4; i++)
                ldsm_x4(a[i], abuf + aoffs[i] + kk*32);
            #pragma unroll
            for (int g = 0; g < 2; g++)
                ldsm_x4_t(b[g], bbuf + boffs[g] + kk*16*(BS_STR*2));
            #pragma unroll
            for (int i = 0; i < 4; i++)
                #pragma unroll
                for (int j = 0; j < 4; j++)
                    mma16816(acc[i][j], a[i], &b[j >> 1][(j & 1) * 2]);
        }
        if (has) {
            int nb = buf ^ 1;
            *(uint4*)&As[nb][sa0] = ra0;  *(uint4*)&As[nb][sa1] = ra1;
            *(uint4*)&Bs[nb][sb0] = rb0;  *(uint4*)&Bs[nb][sb1] = rb1;
            __syncthreads();
            buf = nb;
        }
    }

    // ---- epilogue ----
    #pragma unroll
    for (int i = 0; i < 4; i++) {
        int row = m0 + wm*64 + i*16 + (lane >> 2);
        #pragma unroll
        for (int j = 0; j < 4; j++) {
            int col = n0 + wn*32 + j*8 + (lane & 3)*2;
            float2 bv = *(const float2*)&bias[col];
            float v0 = acc[i][j][0] + bv.x, v1 = acc[i][j][1] + bv.y;
            float v2 = acc[i][j][2] + bv.x, v3 = acc[i][j][3] + bv.y;
            size_t o0 = (size_t)row * N + col;
            size_t o1 = (size_t)(row + 8) * N + col;
            if (EPI == 1) {
                float2 r0 = *(const float2*)&R[o0];
                float2 r1 = *(const float2*)&R[o1];
                v0 += r0.x; v1 += r0.y; v2 += r1.x; v3 += r1.y;
            } else if (EPI == 2) {
                v0 = gelu_exact(v0); v1 = gelu_exact(v1);
                v2 = gelu_exact(v2); v3 = gelu_exact(v3);
            }
            *(float2*)&C[o0] = make_float2(v0, v1);
            *(float2*)&C[o1] = make_float2(v2, v3);
        }
    }
}

// ---------------- self-attention (causal, T=128 keys) -----------------------
__global__ void self_attn_kernel(const float* __restrict__ qkv,
                                 float* __restrict__ out) {
    int q = blockIdx.x;
    int b = blockIdx.y >> 3, h = blockIdx.y & 7;
    int tid = threadIdx.x;              // 128
    int w = tid >> 5, lane = tid & 31;

    __shared__ float sQ[HD];
    __shared__ float sc[TT];
    __shared__ float red[4];
    __shared__ float part[2][HD];

    const float* Qp = qkv + ((size_t)(b*TT + q)) * (3*DD) + h*HD;
    if (tid < HD) sQ[tid] = Qp[tid];
    __syncthreads();

    float s;
    if (tid <= q) {
        const float* Kp = qkv + ((size_t)(b*TT + tid)) * (3*DD) + DD + h*HD;
        float a = 0.f;
        #pragma unroll
        for (int d = 0; d < HD; d++) a += sQ[d] * Kp[d];
        s = a * 0.125f;
    } else s = -1e9f;

    float m = s;
    #pragma unroll
    for (int off = 16; off > 0; off >>= 1) m = fmaxf(m, __shfl_xor_sync(~0u, m, off));
    if (lane == 0) red[w] = m;
    __syncthreads();
    float gm = fmaxf(fmaxf(red[0], red[1]), fmaxf(red[2], red[3]));
    __syncthreads();
    float e = expf(s - gm);
    float su = e;
    #pragma unroll
    for (int off = 16; off > 0; off >>= 1) su += __shfl_xor_sync(~0u, su, off);
    if (lane == 0) red[w] = su;
    sc[tid] = e;
    __syncthreads();
    float gs = red[0] + red[1] + red[2] + red[3];

    int d = tid & 63, half = tid >> 6;
    float a = 0.f;
    int kbase = half * 64;
    for (int kk = 0; kk < 64; kk++) {
        const float* Vp = qkv + ((size_t)(b*TT + kbase + kk)) * (3*DD) + 2*DD + h*HD;
        a += sc[kbase + kk] * Vp[d];
    }
    part[half][d] = a;
    __syncthreads();
    if (tid < HD)
        out[((size_t)(b*TT + q)) * DD + h*HD + tid] =
            (part[0][tid] + part[1][tid]) / gs;
}

// ---------------- cross-attention (M=256 keys) ------------------------------
__global__ void cross_attn_kernel(const float* __restrict__ qbuf,
                                  const float* __restrict__ kv,
                                  float* __restrict__ out) {
    int q = blockIdx.x;
    int b = blockIdx.y >> 3, h = blockIdx.y & 7;
    int tid = threadIdx.x;              // 256
    int w = tid >> 5, lane = tid & 31;

    __shared__ float sQ[HD];
    __shared__ float sc[MM];
    __shared__ float red[8];
    __shared__ float part[4][HD];

    if (tid < HD) sQ[tid] = qbuf[((size_t)(b*TT + q)) * DD + h*HD + tid];
    __syncthreads();

    const float* Kp = kv + ((size_t)(b*MM + tid)) * (2*DD) + h*HD;
    float a = 0.f;
    #pragma unroll
    for (int d = 0; d < HD; d++) a += sQ[d] * Kp[d];
    float s = a * 0.125f;

    float m = s;
    #pragma unroll
    for (int off = 16; off > 0; off >>= 1) m = fmaxf(m, __shfl_xor_sync(~0u, m, off));
    if (lane == 0) red[w] = m;
    __syncthreads();
    float gm = red[0];
    #pragma unroll
    for (int i = 1; i < 8; i++) gm = fmaxf(gm, red[i]);
    __syncthreads();
    float e = expf(s - gm);
    float su = e;
    #pragma unroll
    for (int off = 16; off > 0; off >>= 1) su += __shfl_xor_sync(~0u, su, off);
    if (lane == 0) red[w] = su;
    sc[tid] = e;
    __syncthreads();
    float gs = 0.f;
    #pragma unroll
    for (int i = 0; i < 8; i++) gs += red[i];

    int d = tid & 63, qt = tid >> 6;
    float av = 0.f;
    int kbase = qt * 64;
    for (int kk = 0; kk < 64; kk++) {
        const float* Vp = kv + ((size_t)(b*MM + kbase + kk)) * (2*DD) + DD + h*HD;
        av += sc[kbase + kk] * Vp[d];
    }
    part[qt][d] = av;
    __syncthreads();
    if (tid < HD)
        out[((size_t)(b*TT + q)) * DD + h*HD + tid] =
            (part[0][tid] + part[1][tid] + part[2][tid] + part[3][tid]) / gs;
}

// ---------------- host orchestration ----------------------------------------
static inline void conv_A(const float* src, __nv_bfloat16* dst, int Mr, int K) {
    int total4 = Mr * K / 4;
    convA_kernel<<<(total4 + 255) / 256, 256>>>(src, dst, K, total4);
}
static inline void conv_B(const float* src, __nv_bfloat16* dst, int K, int N) {
    int total4 = K * N / 4;
    convB_kernel<<<(total4 + 255) / 256, 256>>>(src, dst, total4, total4);
}
static inline void run_mma(int epi, const __nv_bfloat16* A, const __nv_bfloat16* B,
                           const float* bias, const float* R, float* C,
                           int M, int N, int K2) {
    dim3 grid(N / GBN, M / GBM);
    if (epi == 0)      mma_gemm<0><<<grid, 256>>>(A, B, bias, R, C, M, N, K2);
    else if (epi == 1) mma_gemm<1><<<grid, 256>>>(A, B, bias, R, C, M, N, K2);
    else               mma_gemm<2><<<grid, 256>>>(A, B, bias, R, C, M, N, K2);
}

extern "C" void kernel_launch(void* const* d_in, const int* in_sizes, int n_in,
                              void* d_out, int out_size) {
    const float* memory  = (const float*)d_in[0];
    const void*  targets = d_in[1];
    const float* tok_emb = (const float*)d_in[2];
    const float* pos_emb = (const float*)d_in[3];
    const float* sa_qkv_w = (const float*)d_in[4];
    const float* sa_qkv_b = (const float*)d_in[5];
    const float* sa_out_w = (const float*)d_in[6];
    const float* sa_out_b = (const float*)d_in[7];
    const float* ca_q_w   = (const float*)d_in[8];
    const float* ca_q_b   = (const float*)d_in[9];
    const float* ca_kv_w  = (const float*)d_in[10];
    const float* ca_kv_b  = (const float*)d_in[11];
    const float* ca_out_w = (const float*)d_in[12];
    const float* ca_out_b = (const float*)d_in[13];
    const float* ffn1_w   = (const float*)d_in[14];
    const float* ffn1_b   = (const float*)d_in[15];
    const float* ffn2_w   = (const float*)d_in[16];
    const float* ffn2_b   = (const float*)d_in[17];
    const float* ln1_g = (const float*)d_in[18];
    const float* ln1_b = (const float*)d_in[19];
    const float* ln2_g = (const float*)d_in[20];
    const float* ln2_b = (const float*)d_in[21];
    const float* ln3_g = (const float*)d_in[22];
    const float* ln3_b = (const float*)d_in[23];
    const float* normf_g = (const float*)d_in[24];
    const float* normf_b = (const float*)d_in[25];
    const float* out_w = (const float*)d_in[26];
    const float* out_b = (const float*)d_in[27];
    float* out = (float*)d_out;

    float *x, *h, *attn, *qb, *qkv, *kv, *ffn;
    __nv_bfloat16 *Ab, *Bb, *memb;
    cudaGetSymbolAddress((void**)&x,    g_x);
    cudaGetSymbolAddress((void**)&h,    g_h);
    cudaGetSymbolAddress((void**)&attn, g_attn);
    cudaGetSymbolAddress((void**)&qb,   g_q);
    cudaGetSymbolAddress((void**)&qkv,  g_qkv);
    cudaGetSymbolAddress((void**)&kv,   g_kv);
    cudaGetSymbolAddress((void**)&ffn,  g_ffn);
    cudaGetSymbolAddress((void**)&Ab,   g_Ab);
    cudaGetSymbolAddress((void**)&Bb,   g_Bb);
    cudaGetSymbolAddress((void**)&memb, g_memb);

    detect_kernel<<<1, 256>>>((const int*)targets);
    embed_kernel<<<(BT*DD + 255) / 256, 256>>>(targets, tok_emb, pos_emb, x);

    // convert encoder memory once (reused every layer)
    conv_A(memory, memb, BM_ROWS, DD);

    dim3 agrid(TT, BB*HH);

    for (int l = 0; l < LL; l++) {
        // ---- self-attention ----
        ln_kernel<<<BT, 256>>>(x, ln1_g + l*DD, ln1_b + l*DD, h);
        conv_A(h, Ab, BT, DD);
        conv_B(sa_qkv_w + (size_t)l*DD*3*DD, Bb, DD, 3*DD);
        run_mma(0, Ab, Bb, sa_qkv_b + (size_t)l*3*DD, nullptr, qkv, BT, 3*DD, 3*DD);
        self_attn_kernel<<<agrid, 128>>>(qkv, attn);
        conv_A(attn, Ab, BT, DD);
        conv_B(sa_out_w + (size_t)l*DD*DD, Bb, DD, DD);
        run_mma(1, Ab, Bb, sa_out_b + (size_t)l*DD, x, x, BT, DD, 3*DD);
        // ---- cross-attention ----
        ln_kernel<<<BT, 256>>>(x, ln2_g + l*DD, ln2_b + l*DD, h);
        conv_A(h, Ab, BT, DD);
        conv_B(ca_q_w + (size_t)l*DD*DD, Bb, DD, DD);
        run_mma(0, Ab, Bb, ca_q_b + (size_t)l*DD, nullptr, qb, BT, DD, 3*DD);
        conv_B(ca_kv_w + (size_t)l*DD*2*DD, Bb, DD, 2*DD);
        run_mma(0, memb, Bb, ca_kv_b + (size_t)l*2*DD, nullptr, kv, BM_ROWS, 2*DD, 3*DD);
        cross_attn_kernel<<<agrid, 256>>>(qb, kv, attn);
        conv_A(attn, Ab, BT, DD);
        conv_B(ca_out_w + (size_t)l*DD*DD, Bb, DD, DD);
        run_mma(1, Ab, Bb, ca_out_b + (size_t)l*DD, x, x, BT, DD, 3*DD);
        // ---- FFN ----
        ln_kernel<<<BT, 256>>>(x, ln3_g + l*DD, ln3_b + l*DD, h);
        conv_A(h, Ab, BT, DD);
        conv_B(ffn1_w + (size_t)l*DD*4*DD, Bb, DD, 4*DD);
        run_mma(2, Ab, Bb, ffn1_b + (size_t)l*4*DD, nullptr, ffn, BT, 4*DD, 3*DD);
        conv_A(ffn, Ab, BT, 4*DD);
        conv_B(ffn2_w + (size_t)l*4*DD*DD, Bb, 4*DD, DD);
        run_mma(1, Ab, Bb, ffn2_b + (size_t)l*DD, x, x, BT, DD, 12*DD);
    }

    // ---- final LN + vocab head ----
    ln_kernel<<<BT, 256>>>(x, normf_g, normf_b, h);
    conv_A(h, Ab, BT, DD);
    conv_B(out_w, Bb, DD, VV);
    run_mma(0, Ab, Bb, out_b, nullptr, out, BT, VV, 3*DD);
}